// round 1
// baseline (speedup 1.0000x reference)
#include <cuda_runtime.h>
#include <cuda_bf16.h>

// Problem constants
#define NA     100000   // atoms
#define NBND   200000   // bonds
#define MAXNB  6
#define AF     133      // atom fdim
#define BF     147      // bond fdim
#define HID    300      // hidden
#define NM     8192     // molecules

// Scratch (device globals — allocation-free per harness rules)
__device__ float g_inp [NBND * HID];   // pre-activation bond messages (persistent across depth)
__device__ float g_bufA[NBND * HID];   // message ping
__device__ float g_bufB[NBND * HID];   // message pong
__device__ float g_pre [NBND * HID];   // a_message[b2a] - message[b2revb]
__device__ float g_amsg[NA   * HID];   // per-atom summed neighbor messages
__device__ float g_hid [NA   * HID];   // atom hiddens

// ---------------------------------------------------------------------------
// GEMM: C[M,N=300] = act( A[M,K] @ B[K,300] (+add) )
// MODE 0: A plain [M,K]
// MODE 1: A = concat(f_atoms[M,133], A2[M,300]) along K (K=433)
// EPI  0: C = val ; C2 = relu(val)            (initial W_i GEMM)
// EPI  1: C = relu(val + addsrc[row,col])     (W_h GEMM, addsrc = g_inp)
// EPI  2: C = relu(val + addsrc[col])         (W_o GEMM, addsrc = bias)
// Tiling: BM=128, BN=64, BK=16, 256 threads, 8x4 per-thread micro-tile.
// ---------------------------------------------------------------------------
#define BM 128
#define BN 64
#define BK 16
#define AP 132   // padded A-tile row length (kills 16-way smem store conflict)

template<int MODE, int EPI>
__global__ __launch_bounds__(256)
void gemm_kernel(const float* __restrict__ A, const float* __restrict__ A2,
                 const float* __restrict__ Bw, const float* __restrict__ addsrc,
                 float* __restrict__ C, float* __restrict__ C2,
                 int M, int K)
{
    const int N = HID;
    __shared__ __align__(16) float As[BK * AP];   // As[k][m], row length AP
    __shared__ __align__(16) float Bs[BK * BN];   // Bs[k][n]

    const int tid = threadIdx.x;          // 0..255
    const int tx  = tid & 15;             // col group: 4 cols each
    const int ty  = tid >> 4;             // row group: 8 rows each
    const int row0 = blockIdx.y * BM;
    const int col0 = blockIdx.x * BN;

    float acc[8][4];
#pragma unroll
    for (int i = 0; i < 8; i++)
#pragma unroll
        for (int j = 0; j < 4; j++) acc[i][j] = 0.f;

    for (int k0 = 0; k0 < K; k0 += BK) {
        // --- load A tile (BM x BK = 2048 elems, 8 per thread) ---
#pragma unroll
        for (int i = 0; i < 8; i++) {
            int e = tid + i * 256;
            int r = e >> 4;          // 0..127
            int c = e & 15;          // 0..15
            int gr = row0 + r;
            int gk = k0 + c;
            float v = 0.f;
            if (gr < M && gk < K) {
                if (MODE == 0) v = A[gr * K + gk];
                else           v = (gk < AF) ? A[gr * AF + gk]
                                             : A2[gr * HID + (gk - AF)];
            }
            As[c * AP + r] = v;
        }
        // --- load B tile (BK x BN = 1024 elems, 4 per thread) ---
#pragma unroll
        for (int i = 0; i < 4; i++) {
            int e = tid + i * 256;
            int r = e >> 6;          // 0..15
            int c = e & 63;          // 0..63
            int gk = k0 + r;
            int gc = col0 + c;
            float v = 0.f;
            if (gk < K && gc < N) v = Bw[gk * N + gc];
            Bs[r * BN + c] = v;
        }
        __syncthreads();

#pragma unroll
        for (int kk = 0; kk < BK; kk++) {
            const float4 a0 = *(const float4*)&As[kk * AP + ty * 8];
            const float4 a1 = *(const float4*)&As[kk * AP + ty * 8 + 4];
            const float4 b0 = *(const float4*)&Bs[kk * BN + tx * 4];
            float a[8] = {a0.x, a0.y, a0.z, a0.w, a1.x, a1.y, a1.z, a1.w};
            float b[4] = {b0.x, b0.y, b0.z, b0.w};
#pragma unroll
            for (int i = 0; i < 8; i++)
#pragma unroll
                for (int j = 0; j < 4; j++)
                    acc[i][j] += a[i] * b[j];
        }
        __syncthreads();
    }

    // --- epilogue ---
#pragma unroll
    for (int i = 0; i < 8; i++) {
        int gr = row0 + ty * 8 + i;
        if (gr >= M) continue;
#pragma unroll
        for (int j = 0; j < 4; j++) {
            int gc = col0 + tx * 4 + j;
            if (gc >= N) continue;
            float v = acc[i][j];
            int idx = gr * N + gc;
            if (EPI == 0) {
                C[idx]  = v;
                C2[idx] = fmaxf(v, 0.f);
            } else if (EPI == 1) {
                v += addsrc[idx];
                C[idx] = fmaxf(v, 0.f);
            } else {
                v += addsrc[gc];
                C[idx] = fmaxf(v, 0.f);
            }
        }
    }
}

// ---------------------------------------------------------------------------
// a_message[a,h] = sum_{j<6} message[a2b[a,j], h]
// ---------------------------------------------------------------------------
__global__ __launch_bounds__(256)
void gather_sum_kernel(const float* __restrict__ msg, const int* __restrict__ a2b,
                       float* __restrict__ amsg)
{
    int idx = blockIdx.x * blockDim.x + threadIdx.x;
    if (idx >= NA * HID) return;
    int a = idx / HID;
    int h = idx - a * HID;
    const int* nb = a2b + a * MAXNB;
    float s = 0.f;
#pragma unroll
    for (int j = 0; j < MAXNB; j++)
        s += msg[nb[j] * HID + h];
    amsg[idx] = s;
}

// ---------------------------------------------------------------------------
// pre[b,h] = a_message[b2a[b], h] - message[b2revb[b], h]
// ---------------------------------------------------------------------------
__global__ __launch_bounds__(256)
void pre_kernel(const float* __restrict__ amsg, const float* __restrict__ msg,
                const int* __restrict__ b2a, const int* __restrict__ b2revb,
                float* __restrict__ pre)
{
    int idx = blockIdx.x * blockDim.x + threadIdx.x;
    if (idx >= NBND * HID) return;
    int b = idx / HID;
    int h = idx - b * HID;
    pre[idx] = amsg[b2a[b] * HID + h] - msg[b2revb[b] * HID + h];
}

// ---------------------------------------------------------------------------
// Per-molecule mean (mol_ids sorted): binary-search range, deterministic sum.
// ---------------------------------------------------------------------------
__global__ __launch_bounds__(256)
void mol_mean_kernel(const float* __restrict__ hidden, const int* __restrict__ mol_ids,
                     float* __restrict__ out)
{
    int m = blockIdx.x;
    __shared__ int s_start, s_end;
    if (threadIdx.x == 0) {
        int lo = 0, hi = NA;
        while (lo < hi) { int mid = (lo + hi) >> 1; if (mol_ids[mid] < m) lo = mid + 1; else hi = mid; }
        s_start = lo;
        hi = NA;
        while (lo < hi) { int mid = (lo + hi) >> 1; if (mol_ids[mid] < m + 1) lo = mid + 1; else hi = mid; }
        s_end = lo;
    }
    __syncthreads();
    const int start = s_start, end = s_end;
    const float inv = 1.f / fmaxf((float)(end - start), 1.f);
    for (int h = threadIdx.x; h < HID; h += blockDim.x) {
        float s = 0.f;
        for (int a = start; a < end; a++)
            s += hidden[a * HID + h];
        out[m * HID + h] = s * inv;
    }
}

// ---------------------------------------------------------------------------
extern "C" void kernel_launch(void* const* d_in, const int* in_sizes, int n_in,
                              void* d_out, int out_size)
{
    const float* f_atoms = (const float*)d_in[0];   // [NA, 133]
    const float* f_bonds = (const float*)d_in[1];   // [NBND, 147]
    const float* W_i     = (const float*)d_in[2];   // [147, 300]
    const float* W_h     = (const float*)d_in[3];   // [300, 300]
    const float* W_o     = (const float*)d_in[4];   // [433, 300]
    const float* b_o     = (const float*)d_in[5];   // [300]
    const int*   a2b     = (const int*)d_in[6];     // [NA, 6]
    const int*   b2a     = (const int*)d_in[7];     // [NBND]
    const int*   b2revb  = (const int*)d_in[8];     // [NBND]
    const int*   mol_ids = (const int*)d_in[9];     // [NA]
    float* out = (float*)d_out;                     // [NM, 300]

    float *inp, *bufA, *bufB, *pre, *amsg, *hid;
    cudaGetSymbolAddress((void**)&inp,  g_inp);
    cudaGetSymbolAddress((void**)&bufA, g_bufA);
    cudaGetSymbolAddress((void**)&bufB, g_bufB);
    cudaGetSymbolAddress((void**)&pre,  g_pre);
    cudaGetSymbolAddress((void**)&amsg, g_amsg);
    cudaGetSymbolAddress((void**)&hid,  g_hid);

    const dim3 blk(256);
    const dim3 grid_b((HID + BN - 1) / BN, (NBND + BM - 1) / BM);  // (5, 1563)
    const dim3 grid_a((HID + BN - 1) / BN, (NA + BM - 1) / BM);    // (5, 782)
    const int n_ah = NA * HID;
    const int n_bh = NBND * HID;

    // 1) inp = f_bonds @ W_i ; msg0 = relu(inp)
    gemm_kernel<0, 0><<<grid_b, blk>>>(f_bonds, nullptr, W_i, nullptr,
                                       inp, bufA, NBND, BF);

    // 2) 3x message-passing iterations (ping-pong bufA/bufB)
    float* cur = bufA;
    float* nxt = bufB;
    for (int d = 0; d < 3; d++) {
        gather_sum_kernel<<<(n_ah + 255) / 256, blk>>>(cur, a2b, amsg);
        pre_kernel<<<(n_bh + 255) / 256, blk>>>(amsg, cur, b2a, b2revb, pre);
        gemm_kernel<0, 1><<<grid_b, blk>>>(pre, nullptr, W_h, inp,
                                           nxt, nullptr, NBND, HID);
        float* t = cur; cur = nxt; nxt = t;
    }

    // 3) final neighbor sum + readout GEMM (concat A) + bias + relu
    gather_sum_kernel<<<(n_ah + 255) / 256, blk>>>(cur, a2b, amsg);
    gemm_kernel<1, 2><<<grid_a, blk>>>(f_atoms, amsg, W_o, b_o,
                                       hid, nullptr, NA, AF + HID);

    // 4) per-molecule mean
    mol_mean_kernel<<<NM, blk>>>(hid, mol_ids, out);
}